// round 4
// baseline (speedup 1.0000x reference)
#include <cuda_runtime.h>
#include <cuda_bf16.h>
#include <cstdint>
#include <math.h>

#define DINL __device__ __forceinline__

// ---------------- problem sizes ----------------
constexpr int B_ = 32, S_ = 1024, D_ = 768;
constexpr int HALF = D_ / 2;

// ---------------- scratch (static device globals) ----------------
__device__ __align__(16) __nv_bfloat16 g_xh[B_ * S_ * D_], g_xl[B_ * S_ * D_];
__device__ __align__(16) __nv_bfloat16 g_Wh[3][D_ * D_], g_Wl[3][D_ * D_];
__device__ __align__(16) __nv_bfloat16 g_Qh[B_ * S_ * D_], g_Ql[B_ * S_ * D_];
__device__ __align__(16) __nv_bfloat16 g_Kh[B_ * S_ * D_], g_Kl[B_ * S_ * D_];
__device__ __align__(16) __nv_bfloat16 g_Vth[B_ * D_ * S_], g_Vtl[B_ * D_ * S_];
__device__ __align__(16) float g_S[B_ * S_ * S_];
__device__ __align__(16) __nv_bfloat16 g_Ph[B_ * S_ * S_], g_Pl[B_ * S_ * S_];
__device__ float g_cosT[S_ * HALF], g_sinT[S_ * HALF];

// ---------------- tiling ----------------
// CTA tile 128x128, K-chunk 32 bf16. smem rows padded: 64B data + 16B pad.
constexpr int ROWB  = 80;                 // bytes per smem row
constexpr int TILEB = 128 * ROWB;         // 10240 B per tile
constexpr int BUFB  = 4 * TILEB;          // Ah, Al, Bh, Bl = 40960 B
constexpr int SMEM_G = 2 * BUFB;          // double buffer = 81920 B

// ---------------- helpers ----------------
DINL uint32_t smem_u32(const void* p) {
    uint32_t a;
    asm("{ .reg .u64 t; cvta.to.shared.u64 t, %1; cvt.u32.u64 %0, t; }" : "=r"(a) : "l"(p));
    return a;
}

DINL uint32_t hi_pack(float a, float b) {  // {bf16_trunc(b), bf16_trunc(a)} low=a
    uint32_t r;
    asm("prmt.b32 %0, %1, %2, 0x7632;" : "=r"(r)
        : "r"(__float_as_uint(a)), "r"(__float_as_uint(b)));
    return r;
}

DINL uint32_t lo_pack(float a, float b) {  // rn(residual), low=a
    float la = a - __uint_as_float(__float_as_uint(a) & 0xffff0000u);
    float lb = b - __uint_as_float(__float_as_uint(b) & 0xffff0000u);
    uint32_t r;
    asm("cvt.rn.bf16x2.f32 %0, %1, %2;" : "=r"(r) : "f"(lb), "f"(la));
    return r;
}

DINL void mma16(float c[4], const uint32_t a[4], const uint32_t b[2]) {
    asm volatile(
        "mma.sync.aligned.m16n8k16.row.col.f32.bf16.bf16.f32 "
        "{%0,%1,%2,%3}, {%4,%5,%6,%7}, {%8,%9}, {%0,%1,%2,%3};\n"
        : "+f"(c[0]), "+f"(c[1]), "+f"(c[2]), "+f"(c[3])
        : "r"(a[0]), "r"(a[1]), "r"(a[2]), "r"(a[3]), "r"(b[0]), "r"(b[1]));
}

DINL void ldsm4(uint32_t r[4], uint32_t addr) {
    asm volatile("ldmatrix.sync.aligned.m8n8.x4.shared.b16 {%0,%1,%2,%3}, [%4];"
                 : "=r"(r[0]), "=r"(r[1]), "=r"(r[2]), "=r"(r[3]) : "r"(addr));
}

DINL void cpa16(uint32_t dst, const void* src) {
    asm volatile("cp.async.cg.shared.global [%0], [%1], 16;" :: "r"(dst), "l"(src) : "memory");
}

// load one 128x32 bf16 tile into padded smem via cp.async (2 chunks/thread)
template <int LDK>
DINL void load_tile(const __nv_bfloat16* __restrict__ g, int kt, uint32_t sdst, int tid) {
#pragma unroll
    for (int i = 0; i < 2; i++) {
        int f = tid + (i << 8);
        int r = f >> 2, ch = f & 3;
        const void* src = (const char*)(g + (size_t)r * LDK + kt * 32) + ch * 16;
        cpa16(sdst + r * ROWB + ch * 16, src);
    }
}

// ---------------- compute one 128x128x32 tile (bf16x3, ldmatrix) ----------------
DINL void compute_tile(uint32_t tb, float c[4][4][4]) {
    const int lane = threadIdx.x & 31, warp = threadIdx.x >> 5;
    const int wm = warp >> 2, wn = warp & 3;
    const uint32_t laneoff = (uint32_t)((lane & 15) * ROWB + ((lane & 16) ? 16 : 0));
#pragma unroll
    for (int kk = 0; kk < 2; kk++) {
        const uint32_t ko = kk * 32;
        uint32_t bh[4][2], bl[4][2];
#pragma unroll
        for (int np = 0; np < 2; np++) {
            uint32_t bd = tb + 2 * TILEB + (wn * 32 + np * 16) * ROWB + laneoff + ko;
            uint32_t q[4];
            ldsm4(q, bd);
            bh[2 * np][0] = q[0]; bh[2 * np + 1][0] = q[1];
            bh[2 * np][1] = q[2]; bh[2 * np + 1][1] = q[3];
            ldsm4(q, bd + TILEB);
            bl[2 * np][0] = q[0]; bl[2 * np + 1][0] = q[1];
            bl[2 * np][1] = q[2]; bl[2 * np + 1][1] = q[3];
        }
#pragma unroll
        for (int mf = 0; mf < 4; mf++) {
            uint32_t ad = tb + (wm * 64 + mf * 16) * ROWB + laneoff + ko;
            uint32_t ah[4], al[4];
            ldsm4(ah, ad);
            ldsm4(al, ad + TILEB);
#pragma unroll
            for (int nf = 0; nf < 4; nf++) {
                mma16(c[mf][nf], ah, bh[nf]);
                mma16(c[mf][nf], ah, bl[nf]);
                mma16(c[mf][nf], al, bh[nf]);
            }
        }
    }
}

// ---------------- GEMM mainloop: double-buffered cp.async ----------------
template <int KT, int LDA, int LDB>
DINL void gemm_main(const __nv_bfloat16* __restrict__ Ah, const __nv_bfloat16* __restrict__ Al,
                    const __nv_bfloat16* __restrict__ Bh, const __nv_bfloat16* __restrict__ Bl,
                    char* sm, float c[4][4][4]) {
    const int tid = threadIdx.x;
    uint32_t sb = smem_u32(sm);

#pragma unroll
    for (int mf = 0; mf < 4; mf++)
#pragma unroll
        for (int nf = 0; nf < 4; nf++)
#pragma unroll
            for (int r = 0; r < 4; r++) c[mf][nf][r] = 0.0f;

    load_tile<LDA>(Ah, 0, sb, tid);
    load_tile<LDA>(Al, 0, sb + TILEB, tid);
    load_tile<LDB>(Bh, 0, sb + 2 * TILEB, tid);
    load_tile<LDB>(Bl, 0, sb + 3 * TILEB, tid);
    asm volatile("cp.async.commit_group;" ::: "memory");
    asm volatile("cp.async.wait_group 0;" ::: "memory");
    __syncthreads();

    for (int kt = 0; kt < KT; kt++) {
        int buf = kt & 1;
        if (kt + 1 < KT) {
            uint32_t nb = sb + (buf ^ 1) * BUFB;
            load_tile<LDA>(Ah, kt + 1, nb, tid);
            load_tile<LDA>(Al, kt + 1, nb + TILEB, tid);
            load_tile<LDB>(Bh, kt + 1, nb + 2 * TILEB, tid);
            load_tile<LDB>(Bl, kt + 1, nb + 3 * TILEB, tid);
            asm volatile("cp.async.commit_group;" ::: "memory");
        }
        compute_tile(sb + buf * BUFB, c);
        if (kt + 1 < KT) {
            asm volatile("cp.async.wait_group 0;" ::: "memory");
            __syncthreads();
        }
    }
}

// ---------------- kernel: fp32 -> bf16 hi/lo split (x, W) ----------------
__global__ void __launch_bounds__(256)
k_conv(const float* __restrict__ src, __nv_bfloat16* __restrict__ dh,
       __nv_bfloat16* __restrict__ dl, int n4) {
    int i = blockIdx.x * 256 + threadIdx.x;
    if (i >= n4) return;
    float4 v = reinterpret_cast<const float4*>(src)[i];
    uint2 h, l;
    h.x = hi_pack(v.x, v.y); h.y = hi_pack(v.z, v.w);
    l.x = lo_pack(v.x, v.y); l.y = lo_pack(v.z, v.w);
    reinterpret_cast<uint2*>(dh)[i] = h;
    reinterpret_cast<uint2*>(dl)[i] = l;
}

// ---------------- kernel: RoPE tables ----------------
__global__ void k_ropetab() {
    int idx = blockIdx.x * 256 + threadIdx.x;
    if (idx >= S_ * HALF) return;
    int s = idx / HALF, i = idx - s * HALF;
    float e = (2.0f * (float)i) / 768.0f;
    float invf = 1.0f / powf(10000.0f, e);
    float ang = (float)s * invf;
    float sn, cs;
    sincosf(ang, &sn, &cs);
    g_cosT[idx] = cs;
    g_sinT[idx] = sn;
}

// ---------------- kernel 1: QKV projection + bias + RoPE -> bf16 hi/lo ----------------
__global__ void __launch_bounds__(256, 2)
k_qkv(const float* __restrict__ bq, const float* __restrict__ bk, const float* __restrict__ bv) {
    extern __shared__ char sm[];
    int z = blockIdx.z;
    const float* bb = (z == 0) ? bq : (z == 1) ? bk : bv;
    const int bm = blockIdx.y * 128, bn = blockIdx.x * 128;

    float c[4][4][4];
    gemm_main<24, D_, D_>(g_xh + (size_t)bm * D_, g_xl + (size_t)bm * D_,
                          g_Wh[z] + (size_t)bn * D_, g_Wl[z] + (size_t)bn * D_, sm, c);

    const int lane = threadIdx.x & 31, warp = threadIdx.x >> 5;
    const int wm = warp >> 2, wn = warp & 3, g = lane >> 2, tg = lane & 3;
    const float qscale = 0.03608439182435161f;  // 1/sqrt(768)
#pragma unroll
    for (int mf = 0; mf < 4; mf++) {
#pragma unroll
        for (int h = 0; h < 2; h++) {
            int r = bm + wm * 64 + mf * 16 + g + h * 8;
            int s = r & (S_ - 1);
            int b = r >> 10;
#pragma unroll
            for (int nf = 0; nf < 4; nf++) {
                int col = bn + wn * 32 + nf * 8 + 2 * tg;
                float2 bia = *reinterpret_cast<const float2*>(bb + col);
                float v0 = c[mf][nf][h * 2 + 0] + bia.x;
                float v1 = c[mf][nf][h * 2 + 1] + bia.y;
                if (z < 2) {
                    int i = col >> 1;
                    float cs = g_cosT[s * HALF + i];
                    float sn = g_sinT[s * HALF + i];
                    float t0 = v0 * cs - v1 * sn;
                    v1 = v0 * sn + v1 * cs;
                    v0 = t0;
                    if (z == 0) { v0 *= qscale; v1 *= qscale; }
                    __nv_bfloat16* Ch = (z == 0) ? g_Qh : g_Kh;
                    __nv_bfloat16* Cl = (z == 0) ? g_Ql : g_Kl;
                    size_t off = (size_t)r * D_ + col;
                    *reinterpret_cast<uint32_t*>(Ch + off) = hi_pack(v0, v1);
                    *reinterpret_cast<uint32_t*>(Cl + off) = lo_pack(v0, v1);
                } else {
                    size_t boff = (size_t)b * D_ * S_;
                    float h0 = __uint_as_float(__float_as_uint(v0) & 0xffff0000u);
                    float h1 = __uint_as_float(__float_as_uint(v1) & 0xffff0000u);
                    g_Vth[boff + (size_t)col * S_ + s]       = __float2bfloat16(h0);
                    g_Vth[boff + (size_t)(col + 1) * S_ + s] = __float2bfloat16(h1);
                    g_Vtl[boff + (size_t)col * S_ + s]       = __float2bfloat16(v0 - h0);
                    g_Vtl[boff + (size_t)(col + 1) * S_ + s] = __float2bfloat16(v1 - h1);
                }
            }
        }
    }
}

// ---------------- kernel 2: scores = (Q*scale) K^T -> fp32 ----------------
__global__ void __launch_bounds__(256, 2)
k_scores() {
    extern __shared__ char sm[];
    int z = blockIdx.z;
    const int bm = blockIdx.y * 128, bn = blockIdx.x * 128;
    size_t ao = (size_t)z * S_ * D_ + (size_t)bm * D_;
    size_t bo = (size_t)z * S_ * D_ + (size_t)bn * D_;
    float* C = g_S + (size_t)z * S_ * S_;

    float c[4][4][4];
    gemm_main<24, D_, D_>(g_Qh + ao, g_Ql + ao, g_Kh + bo, g_Kl + bo, sm, c);

    const int lane = threadIdx.x & 31, warp = threadIdx.x >> 5;
    const int wm = warp >> 2, wn = warp & 3, g = lane >> 2, tg = lane & 3;
#pragma unroll
    for (int mf = 0; mf < 4; mf++) {
#pragma unroll
        for (int h = 0; h < 2; h++) {
            int r = bm + wm * 64 + mf * 16 + g + h * 8;
#pragma unroll
            for (int nf = 0; nf < 4; nf++) {
                int col = bn + wn * 32 + nf * 8 + 2 * tg;
                *reinterpret_cast<float2*>(C + (size_t)r * S_ + col) =
                    make_float2(c[mf][nf][h * 2 + 0], c[mf][nf][h * 2 + 1]);
            }
        }
    }
}

// ---------------- kernel 3: row softmax -> bf16 hi/lo P ----------------
__global__ void __launch_bounds__(128)
k_softmax() {
    const float* p = g_S + (size_t)blockIdx.x * S_;
    int t = threadIdx.x;
    float4 a = reinterpret_cast<const float4*>(p)[t];
    float4 b = reinterpret_cast<const float4*>(p)[t + 128];

    float m = fmaxf(fmaxf(fmaxf(a.x, a.y), fmaxf(a.z, a.w)),
                    fmaxf(fmaxf(b.x, b.y), fmaxf(b.z, b.w)));
#pragma unroll
    for (int o = 16; o > 0; o >>= 1) m = fmaxf(m, __shfl_xor_sync(0xffffffffu, m, o));
    __shared__ float r1[4], r2[4];
    if ((t & 31) == 0) r1[t >> 5] = m;
    __syncthreads();
    m = fmaxf(fmaxf(r1[0], r1[1]), fmaxf(r1[2], r1[3]));

    a.x = expf(a.x - m); a.y = expf(a.y - m); a.z = expf(a.z - m); a.w = expf(a.w - m);
    b.x = expf(b.x - m); b.y = expf(b.y - m); b.z = expf(b.z - m); b.w = expf(b.w - m);
    float s = a.x + a.y + a.z + a.w + b.x + b.y + b.z + b.w;
#pragma unroll
    for (int o = 16; o > 0; o >>= 1) s += __shfl_xor_sync(0xffffffffu, s, o);
    if ((t & 31) == 0) r2[t >> 5] = s;
    __syncthreads();
    s = r2[0] + r2[1] + r2[2] + r2[3];
    float inv = 1.0f / s;
    a.x *= inv; a.y *= inv; a.z *= inv; a.w *= inv;
    b.x *= inv; b.y *= inv; b.z *= inv; b.w *= inv;

    uint32_t* ph = reinterpret_cast<uint32_t*>(g_Ph + (size_t)blockIdx.x * S_);
    uint32_t* pl = reinterpret_cast<uint32_t*>(g_Pl + (size_t)blockIdx.x * S_);
    ph[2 * t]           = hi_pack(a.x, a.y);
    ph[2 * t + 1]       = hi_pack(a.z, a.w);
    ph[2 * t + 256]     = hi_pack(b.x, b.y);
    ph[2 * t + 257]     = hi_pack(b.z, b.w);
    pl[2 * t]           = lo_pack(a.x, a.y);
    pl[2 * t + 1]       = lo_pack(a.z, a.w);
    pl[2 * t + 256]     = lo_pack(b.x, b.y);
    pl[2 * t + 257]     = lo_pack(b.z, b.w);
}

// ---------------- kernel 4: out = P V (NT via transposed V) ----------------
__global__ void __launch_bounds__(256, 2)
k_pv(float* __restrict__ out) {
    extern __shared__ char sm[];
    int z = blockIdx.z;
    const int bm = blockIdx.y * 128, bn = blockIdx.x * 128;
    size_t ao = (size_t)z * S_ * S_ + (size_t)bm * S_;
    size_t bo = (size_t)z * D_ * S_ + (size_t)bn * S_;
    float* C = out + (size_t)z * S_ * D_;

    float c[4][4][4];
    gemm_main<32, S_, S_>(g_Ph + ao, g_Pl + ao, g_Vth + bo, g_Vtl + bo, sm, c);

    const int lane = threadIdx.x & 31, warp = threadIdx.x >> 5;
    const int wm = warp >> 2, wn = warp & 3, g = lane >> 2, tg = lane & 3;
#pragma unroll
    for (int mf = 0; mf < 4; mf++) {
#pragma unroll
        for (int h = 0; h < 2; h++) {
            int r = bm + wm * 64 + mf * 16 + g + h * 8;
#pragma unroll
            for (int nf = 0; nf < 4; nf++) {
                int col = bn + wn * 32 + nf * 8 + 2 * tg;
                *reinterpret_cast<float2*>(C + (size_t)r * D_ + col) =
                    make_float2(c[mf][nf][h * 2 + 0], c[mf][nf][h * 2 + 1]);
            }
        }
    }
}

// ---------------- launch ----------------
extern "C" void kernel_launch(void* const* d_in, const int* in_sizes, int n_in,
                              void* d_out, int out_size) {
    const float* x  = (const float*)d_in[0];
    const float* Wq = (const float*)d_in[1];
    const float* bq = (const float*)d_in[2];
    const float* Wk = (const float*)d_in[3];
    const float* bk = (const float*)d_in[4];
    const float* Wv = (const float*)d_in[5];
    const float* bv = (const float*)d_in[6];
    float* out = (float*)d_out;

    cudaFuncSetAttribute(k_qkv,    cudaFuncAttributeMaxDynamicSharedMemorySize, SMEM_G);
    cudaFuncSetAttribute(k_scores, cudaFuncAttributeMaxDynamicSharedMemorySize, SMEM_G);
    cudaFuncSetAttribute(k_pv,     cudaFuncAttributeMaxDynamicSharedMemorySize, SMEM_G);

    // device-pointer getters are not needed: __device__ globals are directly addressable
    // from kernels; k_conv writes into them via pointers obtained on device side.
    k_ropetab<<<(S_ * HALF + 255) / 256, 256>>>();

    // conversion kernels (x + 3 weights); device globals accessed via helper kernels
    {
        // x: B_*S_*D_ floats
        int n4 = (B_ * S_ * D_) / 4;
        // get raw device pointers to globals via cudaGetSymbolAddress is not
        // graph-unsafe (host API, no alloc) — but simpler: small launcher kernels
        // can't take symbol addresses from host without it. Use cudaGetSymbolAddress.
        void *xh, *xl, *wh, *wl;
        cudaGetSymbolAddress(&xh, g_xh);
        cudaGetSymbolAddress(&xl, g_xl);
        k_conv<<<(n4 + 255) / 256, 256>>>(x, (__nv_bfloat16*)xh, (__nv_bfloat16*)xl, n4);

        int w4 = (D_ * D_) / 4;
        cudaGetSymbolAddress(&wh, g_Wh);
        cudaGetSymbolAddress(&wl, g_Wl);
        __nv_bfloat16* Wh0 = (__nv_bfloat16*)wh;
        __nv_bfloat16* Wl0 = (__nv_bfloat16*)wl;
        k_conv<<<(w4 + 255) / 256, 256>>>(Wq, Wh0,             Wl0,             w4);
        k_conv<<<(w4 + 255) / 256, 256>>>(Wk, Wh0 + D_ * D_,   Wl0 + D_ * D_,   w4);
        k_conv<<<(w4 + 255) / 256, 256>>>(Wv, Wh0 + 2 * D_ * D_, Wl0 + 2 * D_ * D_, w4);
    }

    k_qkv<<<dim3(D_ / 128, (B_ * S_) / 128, 3), 256, SMEM_G>>>(bq, bk, bv);
    k_scores<<<dim3(S_ / 128, S_ / 128, B_), 256, SMEM_G>>>();
    k_softmax<<<dim3(B_ * S_), 128>>>();
    k_pv<<<dim3(D_ / 128, S_ / 128, B_), 256, SMEM_G>>>(out);
}